// round 5
// baseline (speedup 1.0000x reference)
#include <cuda_runtime.h>
#include <math.h>

#define D 128
#define G 256
#define BMAX 8192
#define CHUNK 8        // nodes per warp in the streaming phase
#define PRE_BLOCKS 16  // blocks that fold Wp/bp -> g_w/g_c

__device__ float g_w[D];        // Wp @ We[:G]
__device__ float g_c;           // bp . We[:G]
__device__ float g_accum[BMAX]; // zero at load; combine re-zeroes each replay
__device__ float g_src[BMAX];   // src-embed dot per graph
__device__ int   g_flag;        // precompute-done counter (reset each replay)
__device__ int   g_done;        // block-completion counter (reset each replay)

// ---------------------------------------------------------------------------
// Single fused kernel.
//   blocks [0, PRE):                    fold weights (8 warps -> 8 g_w rows)
//   blocks [PRE, PRE+srcBlocks):        src-embed gather (independent of g_w)
//   blocks [PRE+srcBlocks, total):      node streaming (spin on g_flag first)
//   last block to finish:               combine -> out, reset flags
// ---------------------------------------------------------------------------
__global__ void __launch_bounds__(256)
dgmg_fused(const float* __restrict__ hv,
           const float* __restrict__ Wg,
           const float* __restrict__ bg,
           const float* __restrict__ Wp,
           const float* __restrict__ bp,
           const float* __restrict__ We,
           const float* __restrict__ be,
           const int*   __restrict__ seg,
           const int*   __restrict__ last_idx,
           const int*   __restrict__ a,
           float*       __restrict__ out,
           int N, int B, int srcBlocks, int totalBlocks) {
    const int lane   = threadIdx.x & 31;
    const int warpIB = threadIdx.x >> 5;
    const int bx     = blockIdx.x;

    if (bx < PRE_BLOCKS) {
        // ---------------- precompute branch ----------------
        const int gw = bx * 8 + warpIB;   // g_w row this warp computes
        {
            const float* row = Wp + (size_t)gw * G;
            float s = 0.0f;
            #pragma unroll
            for (int i = 0; i < G / 32; i++) {
                int idx = lane + 32 * i;
                s += row[idx] * We[idx];
            }
            #pragma unroll
            for (int off = 16; off > 0; off >>= 1)
                s += __shfl_xor_sync(0xffffffffu, s, off);
            if (lane == 0) g_w[gw] = s;
        }
        if (bx == 0 && warpIB == 0) {
            float s = 0.0f;
            #pragma unroll
            for (int i = 0; i < G / 32; i++) {
                int idx = lane + 32 * i;
                s += bp[idx] * We[idx];
            }
            #pragma unroll
            for (int off = 16; off > 0; off >>= 1)
                s += __shfl_xor_sync(0xffffffffu, s, off);
            if (lane == 0) g_c = s;
        }
        __syncthreads();
        __threadfence();
        if (threadIdx.x == 0) atomicAdd(&g_flag, 1);
    } else if (bx < PRE_BLOCKS + srcBlocks) {
        // ---------------- src-embed gather branch ----------------
        const int b = (bx - PRE_BLOCKS) * 8 + warpIB;
        if (b < B) {
            const int li = __ldg(last_idx + b);
            const float4 h  = reinterpret_cast<const float4*>(hv + (size_t)li * D)[lane];
            const float4 we = reinterpret_cast<const float4*>(We + G)[lane];
            float d = h.x * we.x + h.y * we.y + h.z * we.z + h.w * we.w;
            #pragma unroll
            for (int off = 16; off > 0; off >>= 1)
                d += __shfl_xor_sync(0xffffffffu, d, off);
            if (lane == 0) g_src[b] = d;
        }
    } else {
        // ---------------- node streaming branch ----------------
        // wait for g_w/g_c (usually already done by the time we're scheduled)
        if (threadIdx.x == 0) {
            while (*(volatile int*)&g_flag < PRE_BLOCKS) __nanosleep(64);
        }
        __syncthreads();
        __threadfence();

        const int wid   = (bx - PRE_BLOCKS - srcBlocks) * 8 + warpIB;
        const int start = wid * CHUNK;
        if (start < N) {
            const int cnt = min(CHUNK, N - start);

            const float4* hv4 = reinterpret_cast<const float4*>(hv);
            float4 r[CHUNK];
            #pragma unroll
            for (int j = 0; j < CHUNK; j++) {
                int n = min(start + j, N - 1);
                r[j] = __ldg(hv4 + (size_t)n * 32 + lane);
            }
            const int    segv = __ldg(seg + min(start + (lane & (CHUNK - 1)), N - 1));
            const float4 wg4  = reinterpret_cast<const float4*>(Wg)[lane];
            const float4 w4   = reinterpret_cast<const float4*>(g_w)[lane];
            const float  bg0  = __ldg(bg);
            const float  c0   = g_c;

            int   cur_seg = __shfl_sync(0xffffffffu, segv, 0);
            float acc     = 0.0f;

            #pragma unroll
            for (int j = 0; j < CHUNK; j++) {
                const float4 h = r[j];
                float d1 = h.x * wg4.x + h.y * wg4.y + h.z * wg4.z + h.w * wg4.w;
                float d2 = h.x * w4.x  + h.y * w4.y  + h.z * w4.z  + h.w * w4.w;
                #pragma unroll
                for (int off = 16; off > 0; off >>= 1) {
                    d1 += __shfl_xor_sync(0xffffffffu, d1, off);
                    d2 += __shfl_xor_sync(0xffffffffu, d2, off);
                }
                const float gate    = 1.0f / (1.0f + __expf(-(d1 + bg0)));
                const float contrib = gate * (d2 + c0);
                const int   s_id    = __shfl_sync(0xffffffffu, segv, j);
                if (j < cnt) {
                    if (s_id != cur_seg) {
                        if (lane == 0) atomicAdd(&g_accum[cur_seg], acc);
                        acc     = 0.0f;
                        cur_seg = s_id;
                    }
                    acc += contrib;
                }
            }
            if (lane == 0) atomicAdd(&g_accum[cur_seg], acc);
        }
    }

    // ---------------- grid-completion: last block combines ----------------
    __shared__ int sh_last;
    __threadfence();
    __syncthreads();
    if (threadIdx.x == 0) {
        int d = atomicAdd(&g_done, 1);
        sh_last = (d == totalBlocks - 1) ? 1 : 0;
    }
    __syncthreads();
    if (sh_last) {
        __threadfence();
        const float be0 = be[0];
        for (int b = threadIdx.x; b < B; b += blockDim.x) {
            float logit = g_accum[b] + g_src[b] + be0;
            g_accum[b] = 0.0f;     // reset for next replay
            float x = (a[b] != 0) ? logit : -logit;
            float ls = (x >= 0.0f) ? -log1pf(expf(-x)) : (x - log1pf(expf(x)));
            out[b] = ls;
        }
        __syncthreads();
        if (threadIdx.x == 0) {
            g_flag = 0;            // reset for next replay
            g_done = 0;
        }
    }
}

// ---------------------------------------------------------------------------
extern "C" void kernel_launch(void* const* d_in, const int* in_sizes, int n_in,
                              void* d_out, int out_size) {
    const float* hv       = (const float*)d_in[0];
    const float* Wg       = (const float*)d_in[1];
    const float* bg       = (const float*)d_in[2];
    const float* Wp       = (const float*)d_in[3];
    const float* bp       = (const float*)d_in[4];
    const float* We       = (const float*)d_in[5];
    const float* be       = (const float*)d_in[6];
    const int*   seg_ids  = (const int*)d_in[7];
    const int*   last_idx = (const int*)d_in[8];
    const int*   a        = (const int*)d_in[9];
    float* out = (float*)d_out;

    const int N = in_sizes[0] / D;
    const int B = in_sizes[8];

    const int srcBlocks  = (B + 7) / 8;
    const int nodeWarps  = (N + CHUNK - 1) / CHUNK;
    const int nodeBlocks = (nodeWarps + 7) / 8;
    const int total      = PRE_BLOCKS + srcBlocks + nodeBlocks;

    dgmg_fused<<<total, 256>>>(hv, Wg, bg, Wp, bp, We, be,
                               seg_ids, last_idx, a, out,
                               N, B, srcBlocks, total);
}

// round 6
// speedup vs baseline: 1.5615x; 1.5615x over previous
#include <cuda_runtime.h>
#include <math.h>

#define D 128
#define G 256
#define BMAX 8192
#define CHUNK 4   // nodes per warp, front-batched loads

__device__ float g_w[D];        // Wp @ We[:G]
__device__ float g_c;           // bp . We[:G]
__device__ float g_accum[BMAX]; // zero at module load; finalize re-zeroes after use

// ---------------------------------------------------------------------------
// Kernel 1: fold Wp/bp into We's graph-embed half.
// warps 0..127 -> g_w[warp]; warp 128 -> g_c.
// ---------------------------------------------------------------------------
__global__ void dgmg_precompute(const float* __restrict__ Wp,
                                const float* __restrict__ bp,
                                const float* __restrict__ We) {
    int gt   = blockIdx.x * blockDim.x + threadIdx.x;
    int gw   = gt >> 5;
    int lane = gt & 31;
    if (gw < D) {
        const float* row = Wp + (size_t)gw * G;
        float s = 0.0f;
        #pragma unroll
        for (int i = 0; i < G / 32; i++) {
            int idx = lane + 32 * i;
            s += row[idx] * We[idx];
        }
        #pragma unroll
        for (int off = 16; off > 0; off >>= 1)
            s += __shfl_xor_sync(0xffffffffu, s, off);
        if (lane == 0) g_w[gw] = s;
    } else if (gw == D) {
        float s = 0.0f;
        #pragma unroll
        for (int i = 0; i < G / 32; i++) {
            int idx = lane + 32 * i;
            s += bp[idx] * We[idx];
        }
        #pragma unroll
        for (int off = 16; off > 0; off >>= 1)
            s += __shfl_xor_sync(0xffffffffu, s, off);
        if (lane == 0) g_c = s;
    }
}

// ---------------------------------------------------------------------------
// Kernel 2: stream hv. One warp = CHUNK consecutive nodes, loads front-batched.
// Only the gate dot (d1) is reduced per node (xor butterfly -> sum in all
// lanes). Each lane keeps a per-lane partial of  sum_n gate_n*(d2_lane + c0/32)
// per segment run; cross-lane reduce + atomicAdd only at run boundaries.
// ---------------------------------------------------------------------------
__global__ void __launch_bounds__(256)
dgmg_node_pass(const float* __restrict__ hv,
               const float* __restrict__ Wg,
               const float* __restrict__ bg,
               const int*   __restrict__ seg,
               int N) {
    const int lane = threadIdx.x & 31;
    const int wid  = blockIdx.x * (blockDim.x >> 5) + (threadIdx.x >> 5);

    const int start = wid * CHUNK;
    if (start >= N) return;
    const int cnt = min(CHUNK, N - start);

    // front-batched independent loads
    const float4* hv4 = reinterpret_cast<const float4*>(hv);
    float4 r[CHUNK];
    #pragma unroll
    for (int j = 0; j < CHUNK; j++) {
        int n = min(start + j, N - 1);
        r[j] = __ldg(hv4 + (size_t)n * 32 + lane);
    }
    const int    segv = __ldg(seg + min(start + (lane & (CHUNK - 1)), N - 1));
    const float4 wg4  = reinterpret_cast<const float4*>(Wg)[lane];
    const float4 w4   = reinterpret_cast<const float4*>(g_w)[lane];
    const float  bg0  = __ldg(bg);
    const float  c0l  = g_c * (1.0f / 32.0f);   // distributed across lanes

    int   cur_seg = __shfl_sync(0xffffffffu, segv, 0);
    float accL    = 0.0f;                        // per-lane partial

    #pragma unroll
    for (int j = 0; j < CHUNK; j++) {
        const float4 h = r[j];

        // gate dot: needs full reduce (xor butterfly -> sum in every lane)
        float d1 = h.x * wg4.x + h.y * wg4.y + h.z * wg4.z + h.w * wg4.w;
        #pragma unroll
        for (int off = 16; off > 0; off >>= 1)
            d1 += __shfl_xor_sync(0xffffffffu, d1, off);
        const float gate = 1.0f / (1.0f + __expf(-(d1 + bg0)));

        // projection dot: stays lane-partial
        const float d2L = h.x * w4.x + h.y * w4.y + h.z * w4.z + h.w * w4.w;

        const int s_id = __shfl_sync(0xffffffffu, segv, j);
        if (j < cnt) {
            if (s_id != cur_seg) {
                float red = accL;
                #pragma unroll
                for (int off = 16; off > 0; off >>= 1)
                    red += __shfl_xor_sync(0xffffffffu, red, off);
                if (lane == 0) atomicAdd(&g_accum[cur_seg], red);
                accL    = 0.0f;
                cur_seg = s_id;
            }
            accL += gate * (d2L + c0l);
        }
    }
    {
        float red = accL;
        #pragma unroll
        for (int off = 16; off > 0; off >>= 1)
            red += __shfl_xor_sync(0xffffffffu, red, off);
        if (lane == 0) atomicAdd(&g_accum[cur_seg], red);
    }
}

// ---------------------------------------------------------------------------
// Kernel 3: one warp per graph. Gather src embedding, dot with We[G:],
// combine with accumulated graph term, stable log-sigmoid, pick by a.
// Re-zeroes g_accum[b] for the next graph replay.
// ---------------------------------------------------------------------------
__global__ void __launch_bounds__(256)
dgmg_finalize(const float* __restrict__ hv,
              const float* __restrict__ We,
              const float* __restrict__ be,
              const int*   __restrict__ last_idx,
              const int*   __restrict__ a,
              float*       __restrict__ out,
              int B) {
    const int lane = threadIdx.x & 31;
    const int b = blockIdx.x * (blockDim.x >> 5) + (threadIdx.x >> 5);
    if (b >= B) return;

    const int li = __ldg(last_idx + b);
    const float4 h  = reinterpret_cast<const float4*>(hv + (size_t)li * D)[lane];
    const float4 we = reinterpret_cast<const float4*>(We + G)[lane];

    float d = h.x * we.x + h.y * we.y + h.z * we.z + h.w * we.w;
    #pragma unroll
    for (int off = 16; off > 0; off >>= 1)
        d += __shfl_xor_sync(0xffffffffu, d, off);

    if (lane == 0) {
        float logit = g_accum[b] + d + be[0];
        g_accum[b] = 0.0f;   // reset for next replay
        float x = (a[b] != 0) ? logit : -logit;
        float ls = (x >= 0.0f) ? -log1pf(expf(-x)) : (x - log1pf(expf(x)));
        out[b] = ls;
    }
}

// ---------------------------------------------------------------------------
extern "C" void kernel_launch(void* const* d_in, const int* in_sizes, int n_in,
                              void* d_out, int out_size) {
    const float* hv       = (const float*)d_in[0];
    const float* Wg       = (const float*)d_in[1];
    const float* bg       = (const float*)d_in[2];
    const float* Wp       = (const float*)d_in[3];
    const float* bp       = (const float*)d_in[4];
    const float* We       = (const float*)d_in[5];
    const float* be       = (const float*)d_in[6];
    const int*   seg_ids  = (const int*)d_in[7];
    const int*   last_idx = (const int*)d_in[8];
    const int*   a        = (const int*)d_in[9];
    float* out = (float*)d_out;

    const int N = in_sizes[0] / D;
    const int B = in_sizes[8];

    // K1: fold weights (129 warps)
    dgmg_precompute<<<17, 256>>>(Wp, bp, We);

    // K2: node streaming pass (8 warps/block, CHUNK nodes/warp, front-batched)
    int warps  = (N + CHUNK - 1) / CHUNK;
    int blocks = (warps + 7) / 8;
    dgmg_node_pass<<<blocks, 256>>>(hv, Wg, bg, seg_ids, N);

    // K3: per-graph finalize (8 warps/block)
    int fblocks = (B + 7) / 8;
    dgmg_finalize<<<fblocks, 256>>>(hv, We, be, last_idx, a, out, B);
}

// round 7
// speedup vs baseline: 1.7816x; 1.1409x over previous
#include <cuda_runtime.h>
#include <math.h>

#define D 128
#define G 256
#define BMAX 8192
#define CHUNK 4   // nodes per warp, front-batched loads

__device__ float g_w[D];        // Wp @ We[:G]
__device__ float g_c;           // bp . We[:G]
__device__ float g_accum[BMAX]; // zero at module load; combine re-zeroes after use
__device__ float g_src[BMAX];   // src-embed dot per graph

// ---------------------------------------------------------------------------
// Kernel 1: fold Wp/bp into We's graph-embed half.
// warps 0..127 -> g_w[warp]; warp 128 -> g_c.
// ---------------------------------------------------------------------------
__global__ void dgmg_precompute(const float* __restrict__ Wp,
                                const float* __restrict__ bp,
                                const float* __restrict__ We) {
    int gt   = blockIdx.x * blockDim.x + threadIdx.x;
    int gw   = gt >> 5;
    int lane = gt & 31;
    if (gw < D) {
        const float* row = Wp + (size_t)gw * G;
        float s = 0.0f;
        #pragma unroll
        for (int i = 0; i < G / 32; i++) {
            int idx = lane + 32 * i;
            s += row[idx] * We[idx];
        }
        #pragma unroll
        for (int off = 16; off > 0; off >>= 1)
            s += __shfl_xor_sync(0xffffffffu, s, off);
        if (lane == 0) g_w[gw] = s;
    } else if (gw == D) {
        float s = 0.0f;
        #pragma unroll
        for (int i = 0; i < G / 32; i++) {
            int idx = lane + 32 * i;
            s += bp[idx] * We[idx];
        }
        #pragma unroll
        for (int off = 16; off > 0; off >>= 1)
            s += __shfl_xor_sync(0xffffffffu, s, off);
        if (lane == 0) g_c = s;
    }
}

// ---------------------------------------------------------------------------
// Kernel 2: node stream + independent src-embed gather in one grid.
//   blocks [0, nodeBlocks): one warp = CHUNK nodes, loads front-batched.
//     d1 (gate dot) gets a full butterfly reduce; d2 stays lane-partial and
//     is only reduced at segment boundaries. Fast path when the whole chunk
//     is one segment (~93% of chunks): no per-node seg machinery at all.
//   blocks [nodeBlocks, ...): one warp per graph, gather hv[last_idx] and
//     dot with We[G:] -> g_src. No dependency on g_w/g_accum.
// ---------------------------------------------------------------------------
__global__ void __launch_bounds__(256)
dgmg_main(const float* __restrict__ hv,
          const float* __restrict__ Wg,
          const float* __restrict__ bg,
          const int*   __restrict__ seg,
          const float* __restrict__ We,
          const int*   __restrict__ last_idx,
          int N, int B, int nodeBlocks) {
    const int lane   = threadIdx.x & 31;
    const int warpIB = threadIdx.x >> 5;

    if (blockIdx.x >= nodeBlocks) {
        // ---- src-embed gather ----
        const int b = (blockIdx.x - nodeBlocks) * 8 + warpIB;
        if (b >= B) return;
        const int li = __ldg(last_idx + b);
        const float4 h  = reinterpret_cast<const float4*>(hv + (size_t)li * D)[lane];
        const float4 we = reinterpret_cast<const float4*>(We + G)[lane];
        float d = h.x * we.x + h.y * we.y + h.z * we.z + h.w * we.w;
        #pragma unroll
        for (int off = 16; off > 0; off >>= 1)
            d += __shfl_xor_sync(0xffffffffu, d, off);
        if (lane == 0) g_src[b] = d;
        return;
    }

    // ---- node streaming ----
    const int wid   = blockIdx.x * 8 + warpIB;
    const int start = wid * CHUNK;
    if (start >= N) return;
    const int cnt = min(CHUNK, N - start);

    const float4* hv4 = reinterpret_cast<const float4*>(hv);
    float4 r[CHUNK];
    #pragma unroll
    for (int j = 0; j < CHUNK; j++) {
        int n = min(start + j, N - 1);
        r[j] = __ldg(hv4 + (size_t)n * 32 + lane);
    }
    const int    segv = __ldg(seg + min(start + (lane & (CHUNK - 1)), N - 1));
    const float4 wg4  = reinterpret_cast<const float4*>(Wg)[lane];
    const float4 w4   = reinterpret_cast<const float4*>(g_w)[lane];
    const float  bg0  = __ldg(bg);
    const float  c0l  = g_c * (1.0f / 32.0f);   // distributed across lanes

    // per-node gate and lane-partial projection
    float gatev[CHUNK], d2Lv[CHUNK];
    #pragma unroll
    for (int j = 0; j < CHUNK; j++) {
        const float4 h = r[j];
        float d1 = h.x * wg4.x + h.y * wg4.y + h.z * wg4.z + h.w * wg4.w;
        #pragma unroll
        for (int off = 16; off > 0; off >>= 1)
            d1 += __shfl_xor_sync(0xffffffffu, d1, off);
        gatev[j] = 1.0f / (1.0f + __expf(-(d1 + bg0)));
        d2Lv[j]  = h.x * w4.x + h.y * w4.y + h.z * w4.z + h.w * w4.w;
    }

    const int s_first = __shfl_sync(0xffffffffu, segv, 0);
    const int s_last  = __shfl_sync(0xffffffffu, segv, cnt - 1);

    if (s_first == s_last) {
        // fast path: whole chunk in one segment
        float accL = 0.0f;
        #pragma unroll
        for (int j = 0; j < CHUNK; j++)
            if (j < cnt) accL += gatev[j] * (d2Lv[j] + c0l);
        #pragma unroll
        for (int off = 16; off > 0; off >>= 1)
            accL += __shfl_xor_sync(0xffffffffu, accL, off);
        if (lane == 0) atomicAdd(&g_accum[s_first], accL);
    } else {
        // slow path: run-length aggregation over the chunk
        int   cur_seg = s_first;
        float accL    = 0.0f;
        #pragma unroll
        for (int j = 0; j < CHUNK; j++) {
            const int s_id = __shfl_sync(0xffffffffu, segv, j);
            if (j < cnt) {
                if (s_id != cur_seg) {
                    float red = accL;
                    #pragma unroll
                    for (int off = 16; off > 0; off >>= 1)
                        red += __shfl_xor_sync(0xffffffffu, red, off);
                    if (lane == 0) atomicAdd(&g_accum[cur_seg], red);
                    accL    = 0.0f;
                    cur_seg = s_id;
                }
                accL += gatev[j] * (d2Lv[j] + c0l);
            }
        }
        float red = accL;
        #pragma unroll
        for (int off = 16; off > 0; off >>= 1)
            red += __shfl_xor_sync(0xffffffffu, red, off);
        if (lane == 0) atomicAdd(&g_accum[cur_seg], red);
    }
}

// ---------------------------------------------------------------------------
// Kernel 3: tiny combine. One thread per graph; resets g_accum for the next
// replay (it is zero at module load for the first call).
// ---------------------------------------------------------------------------
__global__ void __launch_bounds__(256)
dgmg_combine(const float* __restrict__ be,
             const int*   __restrict__ a,
             float*       __restrict__ out,
             int B) {
    const int b = blockIdx.x * blockDim.x + threadIdx.x;
    if (b >= B) return;
    float logit = g_accum[b] + g_src[b] + be[0];
    g_accum[b] = 0.0f;   // reset for next replay
    float x = (a[b] != 0) ? logit : -logit;
    float ls = (x >= 0.0f) ? -log1pf(expf(-x)) : (x - log1pf(expf(x)));
    out[b] = ls;
}

// ---------------------------------------------------------------------------
extern "C" void kernel_launch(void* const* d_in, const int* in_sizes, int n_in,
                              void* d_out, int out_size) {
    const float* hv       = (const float*)d_in[0];
    const float* Wg       = (const float*)d_in[1];
    const float* bg       = (const float*)d_in[2];
    const float* Wp       = (const float*)d_in[3];
    const float* bp       = (const float*)d_in[4];
    const float* We       = (const float*)d_in[5];
    const float* be       = (const float*)d_in[6];
    const int*   seg_ids  = (const int*)d_in[7];
    const int*   last_idx = (const int*)d_in[8];
    const int*   a        = (const int*)d_in[9];
    float* out = (float*)d_out;

    const int N = in_sizes[0] / D;
    const int B = in_sizes[8];

    // K1: fold weights (129 warps)
    dgmg_precompute<<<17, 256>>>(Wp, bp, We);

    // K2: node stream + src gather in one grid
    const int nodeWarps  = (N + CHUNK - 1) / CHUNK;
    const int nodeBlocks = (nodeWarps + 7) / 8;
    const int srcBlocks  = (B + 7) / 8;
    dgmg_main<<<nodeBlocks + srcBlocks, 256>>>(hv, Wg, bg, seg_ids, We,
                                               last_idx, N, B, nodeBlocks);

    // K3: combine
    dgmg_combine<<<(B + 255) / 256, 256>>>(be, a, out, B);
}

// round 9
// speedup vs baseline: 1.9975x; 1.1212x over previous
#include <cuda_runtime.h>
#include <math.h>

#define D 128
#define G 256
#define BMAX 8192
#define CHUNK 4   // nodes per warp, front-batched loads

__device__ float g_w[D];        // Wp @ We[:G]
__device__ float g_c;           // bp . We[:G]
__device__ float g_accum[BMAX]; // zero at module load; combine re-zeroes after use
__device__ float g_src[BMAX];   // src-embed dot per graph

__device__ __forceinline__ float warp_sum(float v) {
    #pragma unroll
    for (int off = 16; off > 0; off >>= 1)
        v += __shfl_xor_sync(0xffffffffu, v, off);
    return v;
}

// ---------------------------------------------------------------------------
// Kernel 1: fold Wp/bp into We's graph-embed half.
// warps 0..127 -> g_w[warp]; warp 128 -> g_c.
// ---------------------------------------------------------------------------
__global__ void dgmg_precompute(const float* __restrict__ Wp,
                                const float* __restrict__ bp,
                                const float* __restrict__ We) {
    int gt   = blockIdx.x * blockDim.x + threadIdx.x;
    int gw   = gt >> 5;
    int lane = gt & 31;
    if (gw < D) {
        const float* row = Wp + (size_t)gw * G;
        float s = 0.0f;
        #pragma unroll
        for (int i = 0; i < G / 32; i++) {
            int idx = lane + 32 * i;
            s += row[idx] * We[idx];
        }
        s = warp_sum(s);
        if (lane == 0) g_w[gw] = s;
    } else if (gw == D) {
        float s = 0.0f;
        #pragma unroll
        for (int i = 0; i < G / 32; i++) {
            int idx = lane + 32 * i;
            s += bp[idx] * We[idx];
        }
        s = warp_sum(s);
        if (lane == 0) g_c = s;
    }
}

// ---------------------------------------------------------------------------
// Kernel 2: node stream + independent src-embed gather in one grid.
//   blocks [0, nodeBlocks): one warp = CHUNK nodes, loads front-batched.
//     d1 (gate dot) gets a full butterfly reduce; d2 stays lane-partial and
//     is reduced only at segment boundaries. Fast path when the whole chunk
//     is one segment (~93% of chunks).
//   blocks [nodeBlocks, ...): one warp per graph, gather hv[last_idx] and
//     dot with We[G:] -> g_src. No dependency on g_w/g_accum.
// ---------------------------------------------------------------------------
__global__ void __launch_bounds__(256)
dgmg_main(const float* __restrict__ hv,
          const float* __restrict__ Wg,
          const float* __restrict__ bg,
          const int*   __restrict__ seg,
          const float* __restrict__ We,
          const int*   __restrict__ last_idx,
          int N, int B, int nodeBlocks) {
    const int lane   = threadIdx.x & 31;
    const int warpIB = threadIdx.x >> 5;

    if (blockIdx.x >= nodeBlocks) {
        // ---- src-embed gather ----
        const int b = (blockIdx.x - nodeBlocks) * 8 + warpIB;
        if (b >= B) return;
        const int li = __ldg(last_idx + b);
        const float4 h  = reinterpret_cast<const float4*>(hv + (size_t)li * D)[lane];
        const float4 we = reinterpret_cast<const float4*>(We + G)[lane];
        float d = h.x * we.x + h.y * we.y + h.z * we.z + h.w * we.w;
        d = warp_sum(d);
        if (lane == 0) g_src[b] = d;
        return;
    }

    // ---- node streaming ----
    const int wid   = blockIdx.x * 8 + warpIB;
    const int start = wid * CHUNK;
    if (start >= N) return;
    const int cnt = min(CHUNK, N - start);

    const float4* hv4 = reinterpret_cast<const float4*>(hv);
    float4 r[CHUNK];
    #pragma unroll
    for (int j = 0; j < CHUNK; j++) {
        int n = min(start + j, N - 1);
        r[j] = __ldg(hv4 + (size_t)n * 32 + lane);
    }
    const int    segv = __ldg(seg + min(start + (lane & (CHUNK - 1)), N - 1));
    const float4 wg4  = reinterpret_cast<const float4*>(Wg)[lane];
    const float4 w4   = reinterpret_cast<const float4*>(g_w)[lane];
    const float  bg0  = __ldg(bg);
    const float  c0l  = g_c * (1.0f / 32.0f);   // distributed across lanes

    // per-node gate and lane-partial projection
    float gatev[CHUNK], d2Lv[CHUNK];
    #pragma unroll
    for (int j = 0; j < CHUNK; j++) {
        const float4 h = r[j];
        float d1 = h.x * wg4.x + h.y * wg4.y + h.z * wg4.z + h.w * wg4.w;
        d1 = warp_sum(d1);
        gatev[j] = __fdividef(1.0f, 1.0f + __expf(-(d1 + bg0)));
        d2Lv[j]  = h.x * w4.x + h.y * w4.y + h.z * w4.z + h.w * w4.w;
    }

    const int s_first = __shfl_sync(0xffffffffu, segv, 0);
    const int s_last  = __shfl_sync(0xffffffffu, segv, cnt - 1);

    if (s_first == s_last) {
        // fast path: whole chunk in one segment
        float accL = 0.0f;
        #pragma unroll
        for (int j = 0; j < CHUNK; j++)
            if (j < cnt) accL += gatev[j] * (d2Lv[j] + c0l);
        accL = warp_sum(accL);
        if (lane == 0) atomicAdd(&g_accum[s_first], accL);
    } else {
        // slow path: run-length aggregation over the chunk
        int   cur_seg = s_first;
        float accL    = 0.0f;
        #pragma unroll
        for (int j = 0; j < CHUNK; j++) {
            const int s_id = __shfl_sync(0xffffffffu, segv, j);
            if (j < cnt) {
                if (s_id != cur_seg) {
                    float red = warp_sum(accL);
                    if (lane == 0) atomicAdd(&g_accum[cur_seg], red);
                    accL    = 0.0f;
                    cur_seg = s_id;
                }
                accL += gatev[j] * (d2Lv[j] + c0l);
            }
        }
        float red = warp_sum(accL);
        if (lane == 0) atomicAdd(&g_accum[cur_seg], red);
    }
}

// ---------------------------------------------------------------------------
// Kernel 3: tiny combine. One thread per graph; resets g_accum for the next
// replay (it is zero at module load for the first call).
// ---------------------------------------------------------------------------
__global__ void __launch_bounds__(256)
dgmg_combine(const float* __restrict__ be,
             const int*   __restrict__ a,
             float*       __restrict__ out,
             int B) {
    const int b = blockIdx.x * blockDim.x + threadIdx.x;
    if (b >= B) return;
    float logit = g_accum[b] + g_src[b] + be[0];
    g_accum[b] = 0.0f;   // reset for next replay
    float x = (a[b] != 0) ? logit : -logit;
    float ls = (x >= 0.0f) ? -log1pf(__expf(-x)) : (x - log1pf(__expf(x)));
    out[b] = ls;
}

// ---------------------------------------------------------------------------
extern "C" void kernel_launch(void* const* d_in, const int* in_sizes, int n_in,
                              void* d_out, int out_size) {
    const float* hv       = (const float*)d_in[0];
    const float* Wg       = (const float*)d_in[1];
    const float* bg       = (const float*)d_in[2];
    const float* Wp       = (const float*)d_in[3];
    const float* bp       = (const float*)d_in[4];
    const float* We       = (const float*)d_in[5];
    const float* be       = (const float*)d_in[6];
    const int*   seg_ids  = (const int*)d_in[7];
    const int*   last_idx = (const int*)d_in[8];
    const int*   a        = (const int*)d_in[9];
    float* out = (float*)d_out;

    const int N = in_sizes[0] / D;
    const int B = in_sizes[8];

    // K1: fold weights (129 warps)
    dgmg_precompute<<<17, 256>>>(Wp, bp, We);

    // K2: node stream + src gather in one grid
    const int nodeWarps  = (N + CHUNK - 1) / CHUNK;
    const int nodeBlocks = (nodeWarps + 7) / 8;
    const int srcBlocks  = (B + 7) / 8;
    dgmg_main<<<nodeBlocks + srcBlocks, 256>>>(hv, Wg, bg, seg_ids, We,
                                               last_idx, N, B, nodeBlocks);

    // K3: combine
    dgmg_combine<<<(B + 255) / 256, 256>>>(be, a, out, B);
}